// round 4
// baseline (speedup 1.0000x reference)
#include <cuda_runtime.h>
#include <cuda_fp16.h>
#include <cstdint>

// ============================================================================
// DigitConvolutionalModel: out = relu(conv3x3(x) @ w1 + b1) @ w2 + b2
// Folded:  out = relu(x @ W1eff + b1) @ w2 + b2,   W1eff = C @ w1   [784,128]
//
// sm_103 (non-'a') build target => NO tcgen05/TMEM. Uses baseline PTX:
//   cp.async (sm_80) + ldmatrix (sm_75) + mma.sync.m16n8k16 f16 (sm_80).
// Precision: A in fp16 (single), B split fp16 hi+lo (2 products, shared A
// fragments). Error ~ A's fp16 rounding only ~ 2.8e-4 << 1e-3.
// ============================================================================

#define B_ROWS   65536
#define K_REAL   784
#define BK       64
#define NCHUNK   13          // 13*64 = 832 >= 784 (zero padded)
#define BM       128
#define BN       128
#define THREADS  256

// ---- dynamic smem layout ----
#define A32_OFF     0          // 128x64 fp32 = 32768
#define A16_OFF     32768      // 128x64 fp16 = 16384 (SW128 swizzled)
#define BHI_OFF     49152      // 128x64 fp16 = 16384 (SW128, [n][k])
#define BLO_OFF     65536      // 16384
#define STAGE_BYTES 81920
#define SM_B1       163840     // 128 fp32
#define SM_W2       164352     // 1280 fp32
#define SM_PACC     169472     // 1280 fp32
#define SMEM_TOTAL  174592

// Pre-split, pre-swizzled W1eff^T tiles: [chunk][hi/lo][128n x 64k] fp16.
__device__ __align__(16) __half g_B[NCHUNK][2][128 * 64];

// -------------------- helpers --------------------
__device__ __forceinline__ uint32_t smem_u32(const void* p) {
    uint32_t a;
    asm("{ .reg .u64 t; cvta.to.shared.u64 t, %1; cvt.u32.u64 %0, t; }" : "=r"(a) : "l"(p));
    return a;
}
__device__ __forceinline__ uint32_t sw128(uint32_t off) {
    return off ^ ((off >> 3) & 0x70);
}
__device__ __forceinline__ void cp_async16(uint32_t dst, const void* src) {
    asm volatile("cp.async.cg.shared.global [%0], [%1], 16;" :: "r"(dst), "l"(src) : "memory");
}
__device__ __forceinline__ void cp_async16_zfill(uint32_t dst, const void* src, int src_bytes) {
    asm volatile("cp.async.cg.shared.global [%0], [%1], 16, %2;"
                 :: "r"(dst), "l"(src), "r"(src_bytes) : "memory");
}
__device__ __forceinline__ void cp_commit() {
    asm volatile("cp.async.commit_group;" ::: "memory");
}
__device__ __forceinline__ void ldmatrix_x4(uint32_t& d0, uint32_t& d1, uint32_t& d2,
                                            uint32_t& d3, uint32_t addr) {
    asm volatile("ldmatrix.sync.aligned.m8n8.x4.shared.b16 {%0,%1,%2,%3}, [%4];"
                 : "=r"(d0), "=r"(d1), "=r"(d2), "=r"(d3) : "r"(addr));
}
__device__ __forceinline__ void mma16816(float* d, const uint32_t* a, const uint32_t* b) {
    asm volatile(
        "mma.sync.aligned.m16n8k16.row.col.f32.f16.f16.f32 "
        "{%0,%1,%2,%3}, {%4,%5,%6,%7}, {%8,%9}, {%0,%1,%2,%3};"
        : "+f"(d[0]), "+f"(d[1]), "+f"(d[2]), "+f"(d[3])
        : "r"(a[0]), "r"(a[1]), "r"(a[2]), "r"(a[3]), "r"(b[0]), "r"(b[1]));
}

// ============================================================================
// Prep: W1eff^T = (C @ w1)^T, split fp16 hi/lo, stored per-chunk SW128-swizzled
// as [n][k] so mma row.col (D = A * B^T with B=[N,K]) applies directly.
// ============================================================================
__global__ void prep_kernel(const float* __restrict__ conv_w, const float* __restrict__ w1) {
    int idx = blockIdx.x * blockDim.x + threadIdx.x;
    if (idx >= NCHUNK * 128 * 64) return;
    int chunk = idx >> 13;
    int rem = idx & 8191;
    int n = rem >> 6;          // output-feature index (row of B^T)
    int kk = rem & 63;         // k within chunk
    int k = chunk * 64 + kk;
    float v = 0.f;
    if (k < K_REAL) {
        int r = k / 28, c = k % 28;
        #pragma unroll
        for (int di = 0; di < 3; di++) {
            int oi = r - di;
            if (oi < 0 || oi > 25) continue;
            #pragma unroll
            for (int dj = 0; dj < 3; dj++) {
                int oj = c - dj;
                if (oj < 0 || oj > 25) continue;
                v += conv_w[di * 3 + dj] * w1[(oi * 26 + oj) * 128 + n];
            }
        }
    }
    __half hi = __float2half_rn(v);
    __half lo = __float2half_rn(v - __half2float(hi));
    uint32_t sw = sw128((uint32_t)(n * 128 + kk * 2));
    g_B[chunk][0][sw >> 1] = hi;
    g_B[chunk][1][sw >> 1] = lo;
}

// ============================================================================
// Main kernel: 128-row M tile per CTA, full N=128, K pipelined in 64-chunks.
// ============================================================================
__global__ __launch_bounds__(THREADS)
void digitconv_main(const float* __restrict__ x, const float* __restrict__ b1,
                    const float* __restrict__ w2, const float* __restrict__ b2,
                    float* __restrict__ out) {
    extern __shared__ char smem[];
    const uint32_t sbase = smem_u32(smem);
    const int tid = threadIdx.x;
    const int wid = tid >> 5;
    const int lane = tid & 31;
    const int wm = (wid & 3) * 32;       // warp m offset (4 groups)
    const int wn = (wid >> 2) * 64;      // warp n offset (2 groups)
    const size_t m0 = (size_t)blockIdx.x * BM;

    float* b1s  = (float*)(smem + SM_B1);
    float* w2s  = (float*)(smem + SM_W2);
    float* pacc = (float*)(smem + SM_PACC);

    if (tid < 128) b1s[tid] = b1[tid];
    for (int i = tid; i < 1280; i += THREADS) { w2s[i] = w2[i]; pacc[i] = 0.f; }

    float acc[2][8][4];
    #pragma unroll
    for (int tm = 0; tm < 2; tm++)
        #pragma unroll
        for (int tn = 0; tn < 8; tn++)
            #pragma unroll
            for (int e = 0; e < 4; e++) acc[tm][tn][e] = 0.f;

    // ---- cp.async issue for one chunk into stage s ----
    auto issue_chunk = [&](int c, int s) {
        const uint32_t st = sbase + s * STAGE_BYTES;
        const int kbase = c * BK;
        #pragma unroll
        for (int q = 0; q < 8; q++) {
            int i = q * THREADS + tid;        // 0..2047 float4s of A
            int row = i >> 4;
            int c4 = i & 15;
            int gcol = kbase + c4 * 4;
            int zf = (gcol < K_REAL) ? 16 : 0;
            const float* src = x + (m0 + row) * K_REAL + (zf ? gcol : 0);
            cp_async16_zfill(st + A32_OFF + i * 16, src, zf);
        }
        const char* gb = (const char*)&g_B[c][0][0];   // 32KB: hi then lo
        #pragma unroll
        for (int q = 0; q < 8; q++) {
            int i = q * THREADS + tid;        // 0..2047 x 16B
            cp_async16(st + BHI_OFF + i * 16, gb + i * 16);
        }
        cp_commit();
    };

    issue_chunk(0, 0);
    issue_chunk(1, 1);

    for (int c = 0; c < NCHUNK; c++) {
        const int s = c & 1;
        if (c < NCHUNK - 1)
            asm volatile("cp.async.wait_group 1;" ::: "memory");
        else
            asm volatile("cp.async.wait_group 0;" ::: "memory");
        __syncthreads();

        // ---- convert A fp32 -> fp16 (SW128 swizzled) ----
        {
            const float4* a32 = (const float4*)(smem + s * STAGE_BYTES + A32_OFF);
            char* a16 = smem + s * STAGE_BYTES + A16_OFF;
            #pragma unroll
            for (int q = 0; q < 8; q++) {
                int i = q * THREADS + tid;
                float4 v = a32[i];
                int row = i >> 4;
                int c4 = i & 15;
                __half2 h0 = __floats2half2_rn(v.x, v.y);
                __half2 h1 = __floats2half2_rn(v.z, v.w);
                uint2 w;
                w.x = *reinterpret_cast<uint32_t*>(&h0);
                w.y = *reinterpret_cast<uint32_t*>(&h1);
                *reinterpret_cast<uint2*>(a16 + sw128((uint32_t)(row * 128 + c4 * 8))) = w;
            }
        }
        __syncthreads();

        // ---- MMA: 4 k16-steps, shared A frags, B hi + lo products ----
        const uint32_t aB  = sbase + s * STAGE_BYTES + A16_OFF;
        const uint32_t bBh = sbase + s * STAGE_BYTES + BHI_OFF;
        const uint32_t bBl = sbase + s * STAGE_BYTES + BLO_OFF;
        const int sel = lane >> 3;
        #pragma unroll
        for (int ks = 0; ks < 4; ks++) {
            uint32_t afr[2][4];
            #pragma unroll
            for (int tm = 0; tm < 2; tm++) {
                int r = wm + tm * 16 + (lane & 7) + ((sel & 1) << 3);
                int kb = ks * 32 + ((sel >> 1) << 4);
                ldmatrix_x4(afr[tm][0], afr[tm][1], afr[tm][2], afr[tm][3],
                            aB + sw128((uint32_t)(r * 128 + kb)));
            }
            uint32_t bh[8][2], bl[8][2];
            #pragma unroll
            for (int tp = 0; tp < 4; tp++) {
                int r = wn + (2 * tp + (sel >> 1)) * 8 + (lane & 7);
                int kb = ks * 32 + ((sel & 1) << 4);
                uint32_t off = sw128((uint32_t)(r * 128 + kb));
                ldmatrix_x4(bh[2*tp][0], bh[2*tp][1], bh[2*tp+1][0], bh[2*tp+1][1], bBh + off);
                ldmatrix_x4(bl[2*tp][0], bl[2*tp][1], bl[2*tp+1][0], bl[2*tp+1][1], bBl + off);
            }
            #pragma unroll
            for (int tm = 0; tm < 2; tm++)
                #pragma unroll
                for (int tn = 0; tn < 8; tn++) {
                    mma16816(acc[tm][tn], afr[tm], bh[tn]);
                    mma16816(acc[tm][tn], afr[tm], bl[tn]);
                }
        }
        __syncthreads();

        if (c + 2 < NCHUNK) issue_chunk(c + 2, s);
    }

    // ---- Epilogue: relu(D + b1) @ w2, reduce, + b2, store ----
    #pragma unroll
    for (int tm = 0; tm < 2; tm++) {
        #pragma unroll
        for (int half = 0; half < 2; half++) {
            float p[10];
            #pragma unroll
            for (int j = 0; j < 10; j++) p[j] = 0.f;
            int r = wm + tm * 16 + (lane >> 2) + half * 8;
            #pragma unroll
            for (int tn = 0; tn < 8; tn++) {
                #pragma unroll
                for (int e = 0; e < 2; e++) {
                    int col = wn + tn * 8 + ((lane & 3) << 1) + e;
                    float v = acc[tm][tn][half * 2 + e] + b1s[col];
                    v = fmaxf(v, 0.f);
                    #pragma unroll
                    for (int j = 0; j < 10; j++) p[j] = fmaf(v, w2s[col * 10 + j], p[j]);
                }
            }
            #pragma unroll
            for (int j = 0; j < 10; j++) {
                p[j] += __shfl_xor_sync(0xFFFFFFFF, p[j], 1);
                p[j] += __shfl_xor_sync(0xFFFFFFFF, p[j], 2);
            }
            if ((lane & 3) == 0) {
                #pragma unroll
                for (int j = 0; j < 10; j++) atomicAdd(&pacc[r * 10 + j], p[j]);
            }
        }
    }
    __syncthreads();

    for (int i = tid; i < BM * 10; i += THREADS) {
        int r = i / 10, j = i - r * 10;
        out[(m0 + r) * 10 + j] = pacc[i] + __ldg(&b2[j]);
    }
}

// ============================================================================
extern "C" void kernel_launch(void* const* d_in, const int* in_sizes, int n_in,
                              void* d_out, int out_size) {
    const float* x      = (const float*)d_in[0];
    const float* conv_w = (const float*)d_in[1];
    const float* w1     = (const float*)d_in[2];
    const float* b1     = (const float*)d_in[3];
    const float* w2     = (const float*)d_in[4];
    const float* b2     = (const float*)d_in[5];
    float* out = (float*)d_out;

    cudaFuncSetAttribute(digitconv_main,
                         cudaFuncAttributeMaxDynamicSharedMemorySize, SMEM_TOTAL);

    prep_kernel<<<(NCHUNK * 128 * 64 + 255) / 256, 256>>>(conv_w, w1);
    digitconv_main<<<B_ROWS / BM, THREADS, SMEM_TOTAL>>>(x, b1, w2, b2, out);
}

// round 6
// speedup vs baseline: 1.2016x; 1.2016x over previous
#include <cuda_runtime.h>
#include <cuda_fp16.h>
#include <cstdint>

// ============================================================================
// DigitConvolutionalModel: out = relu(conv3x3(x) @ w1 + b1) @ w2 + b2
// Folded:  out = relu(x @ W1eff + b1) @ w2 + b2,   W1eff = C @ w1   [784,128]
//
// R5: single fp16 product (A fp16 x B fp16), BM=64/BN=128 tiles,
// 2 CTAs/SM (regs<=128, smem 88KB), cp.async 2-stage pipeline.
// ============================================================================

#define B_ROWS   65536
#define K_REAL   784
#define BK       64
#define NCHUNK   13          // 13*64 = 832 >= 784 (zero padded)
#define BM       64
#define BN       128
#define THREADS  256

// ---- dynamic smem layout ----
#define A32_OFF     0          // 64x64 fp32 = 16384
#define A16_OFF     16384      // 64x64 fp16 = 8192 (SW128 swizzled)
#define B_OFF       24576      // 128x64 fp16 = 16384 (SW128, [n][k])
#define STAGE_BYTES 40960
#define SM_B1       81920      // 128 fp32 = 512
#define SM_W2       82432      // 1280 fp32 = 5120
#define SM_PACC     87552      // 640 fp32 = 2560
#define SMEM_TOTAL  90112

// Pre-swizzled W1eff^T tiles: [chunk][128n x 64k] fp16 (hi only).
__device__ __align__(16) __half g_B[NCHUNK][128 * 64];

// -------------------- helpers --------------------
__device__ __forceinline__ uint32_t smem_u32(const void* p) {
    uint32_t a;
    asm("{ .reg .u64 t; cvta.to.shared.u64 t, %1; cvt.u32.u64 %0, t; }" : "=r"(a) : "l"(p));
    return a;
}
__device__ __forceinline__ uint32_t sw128(uint32_t off) {
    return off ^ ((off >> 3) & 0x70);
}
__device__ __forceinline__ void cp_async16(uint32_t dst, const void* src) {
    asm volatile("cp.async.cg.shared.global [%0], [%1], 16;" :: "r"(dst), "l"(src) : "memory");
}
__device__ __forceinline__ void cp_async16_zfill(uint32_t dst, const void* src, int src_bytes) {
    asm volatile("cp.async.cg.shared.global [%0], [%1], 16, %2;"
                 :: "r"(dst), "l"(src), "r"(src_bytes) : "memory");
}
__device__ __forceinline__ void cp_commit() {
    asm volatile("cp.async.commit_group;" ::: "memory");
}
__device__ __forceinline__ void ldmatrix_x4(uint32_t& d0, uint32_t& d1, uint32_t& d2,
                                            uint32_t& d3, uint32_t addr) {
    asm volatile("ldmatrix.sync.aligned.m8n8.x4.shared.b16 {%0,%1,%2,%3}, [%4];"
                 : "=r"(d0), "=r"(d1), "=r"(d2), "=r"(d3) : "r"(addr));
}
__device__ __forceinline__ void mma16816(float* d, const uint32_t* a, const uint32_t* b) {
    asm volatile(
        "mma.sync.aligned.m16n8k16.row.col.f32.f16.f16.f32 "
        "{%0,%1,%2,%3}, {%4,%5,%6,%7}, {%8,%9}, {%0,%1,%2,%3};"
        : "+f"(d[0]), "+f"(d[1]), "+f"(d[2]), "+f"(d[3])
        : "r"(a[0]), "r"(a[1]), "r"(a[2]), "r"(a[3]), "r"(b[0]), "r"(b[1]));
}

// ============================================================================
// Prep: W1eff^T = (C @ w1)^T -> fp16, stored per-chunk SW128-swizzled [n][k].
// ============================================================================
__global__ void prep_kernel(const float* __restrict__ conv_w, const float* __restrict__ w1) {
    int idx = blockIdx.x * blockDim.x + threadIdx.x;
    if (idx >= NCHUNK * 128 * 64) return;
    int chunk = idx >> 13;
    int rem = idx & 8191;
    int n = rem >> 6;          // output-feature index (row of B^T)
    int kk = rem & 63;         // k within chunk
    int k = chunk * 64 + kk;
    float v = 0.f;
    if (k < K_REAL) {
        int r = k / 28, c = k % 28;
        #pragma unroll
        for (int di = 0; di < 3; di++) {
            int oi = r - di;
            if (oi < 0 || oi > 25) continue;
            #pragma unroll
            for (int dj = 0; dj < 3; dj++) {
                int oj = c - dj;
                if (oj < 0 || oj > 25) continue;
                v += conv_w[di * 3 + dj] * w1[(oi * 26 + oj) * 128 + n];
            }
        }
    }
    uint32_t sw = sw128((uint32_t)(n * 128 + kk * 2));
    g_B[chunk][sw >> 1] = __float2half_rn(v);
}

// ============================================================================
// Main kernel: 64-row M tile per CTA, full N=128, K pipelined in 64-chunks.
// 8 warps: (wid&3) -> m16 group, (wid>>2) -> n64 group.
// ============================================================================
__global__ __launch_bounds__(THREADS, 2)
void digitconv_main(const float* __restrict__ x, const float* __restrict__ b1,
                    const float* __restrict__ w2, const float* __restrict__ b2,
                    float* __restrict__ out) {
    extern __shared__ char smem[];
    const uint32_t sbase = smem_u32(smem);
    const int tid = threadIdx.x;
    const int wid = tid >> 5;
    const int lane = tid & 31;
    const int wm = (wid & 3) * 16;       // warp m offset (4 groups of 16)
    const int wn = (wid >> 2) * 64;      // warp n offset (2 groups of 64)
    const size_t m0 = (size_t)blockIdx.x * BM;

    float* b1s  = (float*)(smem + SM_B1);
    float* w2s  = (float*)(smem + SM_W2);
    float* pacc = (float*)(smem + SM_PACC);

    if (tid < 128) b1s[tid] = b1[tid];
    for (int i = tid; i < 1280; i += THREADS) w2s[i] = w2[i];
    for (int i = tid; i < BM * 10; i += THREADS) pacc[i] = 0.f;

    float acc[8][4];
    #pragma unroll
    for (int tn = 0; tn < 8; tn++)
        #pragma unroll
        for (int e = 0; e < 4; e++) acc[tn][e] = 0.f;

    // ---- cp.async issue for one chunk into stage s ----
    auto issue_chunk = [&](int c, int s) {
        const uint32_t st = sbase + s * STAGE_BYTES;
        const int kbase = c * BK;
        #pragma unroll
        for (int q = 0; q < 4; q++) {
            int i = q * THREADS + tid;        // 0..1023 float4s of A (64x16)
            int row = i >> 4;
            int c4 = i & 15;
            int gcol = kbase + c4 * 4;
            int zf = (gcol < K_REAL) ? 16 : 0;
            const float* src = x + (m0 + row) * K_REAL + (zf ? gcol : 0);
            cp_async16_zfill(st + A32_OFF + i * 16, src, zf);
        }
        const char* gb = (const char*)&g_B[c][0];   // 16KB
        #pragma unroll
        for (int q = 0; q < 4; q++) {
            int i = q * THREADS + tid;        // 0..1023 x 16B
            cp_async16(st + B_OFF + i * 16, gb + i * 16);
        }
        cp_commit();
    };

    issue_chunk(0, 0);
    issue_chunk(1, 1);

    for (int c = 0; c < NCHUNK; c++) {
        const int s = c & 1;
        if (c < NCHUNK - 1)
            asm volatile("cp.async.wait_group 1;" ::: "memory");
        else
            asm volatile("cp.async.wait_group 0;" ::: "memory");
        __syncthreads();

        // ---- convert A fp32 -> fp16 (SW128 swizzled) ----
        {
            const float4* a32 = (const float4*)(smem + s * STAGE_BYTES + A32_OFF);
            char* a16 = smem + s * STAGE_BYTES + A16_OFF;
            #pragma unroll
            for (int q = 0; q < 4; q++) {
                int i = q * THREADS + tid;
                float4 v = a32[i];
                int row = i >> 4;
                int c4 = i & 15;
                __half2 h0 = __floats2half2_rn(v.x, v.y);
                __half2 h1 = __floats2half2_rn(v.z, v.w);
                uint2 w;
                w.x = *reinterpret_cast<uint32_t*>(&h0);
                w.y = *reinterpret_cast<uint32_t*>(&h1);
                *reinterpret_cast<uint2*>(a16 + sw128((uint32_t)(row * 128 + c4 * 8))) = w;
            }
        }
        __syncthreads();

        // ---- MMA: 4 k16-steps ----
        const uint32_t aB = sbase + s * STAGE_BYTES + A16_OFF;
        const uint32_t bB = sbase + s * STAGE_BYTES + B_OFF;
        const int sel = lane >> 3;
        #pragma unroll
        for (int ks = 0; ks < 4; ks++) {
            uint32_t afr[4];
            {
                int r = wm + (lane & 7) + ((sel & 1) << 3);
                int kb = ks * 32 + ((sel >> 1) << 4);
                ldmatrix_x4(afr[0], afr[1], afr[2], afr[3],
                            aB + sw128((uint32_t)(r * 128 + kb)));
            }
            uint32_t bf[8][2];
            #pragma unroll
            for (int tp = 0; tp < 4; tp++) {
                int r = wn + (2 * tp + (sel >> 1)) * 8 + (lane & 7);
                int kb = ks * 32 + ((sel & 1) << 4);
                ldmatrix_x4(bf[2*tp][0], bf[2*tp][1], bf[2*tp+1][0], bf[2*tp+1][1],
                            bB + sw128((uint32_t)(r * 128 + kb)));
            }
            #pragma unroll
            for (int tn = 0; tn < 8; tn++)
                mma16816(acc[tn], afr, bf[tn]);
        }
        __syncthreads();

        if (c + 2 < NCHUNK) issue_chunk(c + 2, s);
    }

    // ---- Epilogue: relu(D + b1) @ w2, reduce, + b2, store ----
    #pragma unroll
    for (int half = 0; half < 2; half++) {
        float p[10];
        #pragma unroll
        for (int j = 0; j < 10; j++) p[j] = 0.f;
        int r = wm + (lane >> 2) + half * 8;
        #pragma unroll
        for (int tn = 0; tn < 8; tn++) {
            #pragma unroll
            for (int e = 0; e < 2; e++) {
                int col = wn + tn * 8 + ((lane & 3) << 1) + e;
                float v = acc[tn][half * 2 + e] + b1s[col];
                v = fmaxf(v, 0.f);
                #pragma unroll
                for (int j = 0; j < 10; j++) p[j] = fmaf(v, w2s[col * 10 + j], p[j]);
            }
        }
        #pragma unroll
        for (int j = 0; j < 10; j++) {
            p[j] += __shfl_xor_sync(0xFFFFFFFF, p[j], 1);
            p[j] += __shfl_xor_sync(0xFFFFFFFF, p[j], 2);
        }
        if ((lane & 3) == 0) {
            #pragma unroll
            for (int j = 0; j < 10; j++) atomicAdd(&pacc[r * 10 + j], p[j]);
        }
    }
    __syncthreads();

    for (int i = tid; i < BM * 10; i += THREADS) {
        int r = i / 10, j = i - r * 10;
        out[(m0 + r) * 10 + j] = pacc[i] + __ldg(&b2[j]);
    }
}

// ============================================================================
extern "C" void kernel_launch(void* const* d_in, const int* in_sizes, int n_in,
                              void* d_out, int out_size) {
    const float* x      = (const float*)d_in[0];
    const float* conv_w = (const float*)d_in[1];
    const float* w1     = (const float*)d_in[2];
    const float* b1     = (const float*)d_in[3];
    const float* w2     = (const float*)d_in[4];
    const float* b2     = (const float*)d_in[5];
    float* out = (float*)d_out;

    cudaFuncSetAttribute(digitconv_main,
                         cudaFuncAttributeMaxDynamicSharedMemorySize, SMEM_TOTAL);

    prep_kernel<<<(NCHUNK * 128 * 64 + 255) / 256, 256>>>(conv_w, w1);
    digitconv_main<<<B_ROWS / BM, THREADS, SMEM_TOTAL>>>(x, b1, w2, b2, out);
}

// round 9
// speedup vs baseline: 1.2832x; 1.0679x over previous
#include <cuda_runtime.h>
#include <cuda_fp16.h>
#include <cstdint>

// ============================================================================
// DigitConvolutionalModel: out = relu(conv3x3(x) @ w1 + b1) @ w2 + b2
// Folded:  out = relu(x @ W1eff + b1) @ w2 + b2,   W1eff = C @ w1   [784,128]
//
// R7: R6 structure with the double-buffer race fixed:
//   prefetch B(c+1) into the OTHER stage right after the top barrier
//   (MMA(c-1) provably done), A via LDG->regs->fp16 STS, BK=128 pairs,
//   warp tile m32xn32. 2 CTAs/SM.
// ============================================================================

#define B_ROWS   65536
#define K_REAL   784
#define NPAIR    7           // 7 * 128 = 896 >= 784 (zero padded)
#define NCH64    14          // 64-wide B chunks incl. zero pad
#define BM       64
#define BN       128
#define THREADS  256

// ---- dynamic smem layout ----
#define A16_OFF     0          // 2 subs x (64x64 fp16 = 8192) = 16384
#define B_OFF       16384      // 2 subs x (128x64 fp16 = 16384) = 32768
#define STAGE_BYTES 49152
#define SM_B1       98304      // 128 fp32
#define SM_W2       98816      // 1280 fp32
#define SM_PACC     103936     // 640 fp32
#define SMEM_TOTAL  106496     // 104 KB -> 2 CTAs/SM

// Pre-swizzled W1eff^T tiles: [chunk64][128n x 64k] fp16 (chunks 12,13 zero-padded).
__device__ __align__(16) __half g_B[NCH64][128 * 64];

// -------------------- helpers --------------------
__device__ __forceinline__ uint32_t smem_u32(const void* p) {
    uint32_t a;
    asm("{ .reg .u64 t; cvta.to.shared.u64 t, %1; cvt.u32.u64 %0, t; }" : "=r"(a) : "l"(p));
    return a;
}
__device__ __forceinline__ uint32_t sw128(uint32_t off) {
    return off ^ ((off >> 3) & 0x70);
}
__device__ __forceinline__ void cp_async16(uint32_t dst, const void* src) {
    asm volatile("cp.async.cg.shared.global [%0], [%1], 16;" :: "r"(dst), "l"(src) : "memory");
}
__device__ __forceinline__ void cp_commit() {
    asm volatile("cp.async.commit_group;" ::: "memory");
}
__device__ __forceinline__ void ldmatrix_x4(uint32_t& d0, uint32_t& d1, uint32_t& d2,
                                            uint32_t& d3, uint32_t addr) {
    asm volatile("ldmatrix.sync.aligned.m8n8.x4.shared.b16 {%0,%1,%2,%3}, [%4];"
                 : "=r"(d0), "=r"(d1), "=r"(d2), "=r"(d3) : "r"(addr));
}
__device__ __forceinline__ void mma16816(float* d, const uint32_t* a, const uint32_t* b) {
    asm volatile(
        "mma.sync.aligned.m16n8k16.row.col.f32.f16.f16.f32 "
        "{%0,%1,%2,%3}, {%4,%5,%6,%7}, {%8,%9}, {%0,%1,%2,%3};"
        : "+f"(d[0]), "+f"(d[1]), "+f"(d[2]), "+f"(d[3])
        : "r"(a[0]), "r"(a[1]), "r"(a[2]), "r"(a[3]), "r"(b[0]), "r"(b[1]));
}

// ============================================================================
// Prep: W1eff^T = (C @ w1)^T -> fp16, per-64-chunk SW128-swizzled [n][k].
// ============================================================================
__global__ void prep_kernel(const float* __restrict__ conv_w, const float* __restrict__ w1) {
    int idx = blockIdx.x * blockDim.x + threadIdx.x;
    if (idx >= NCH64 * 128 * 64) return;
    int chunk = idx >> 13;
    int rem = idx & 8191;
    int n = rem >> 6;
    int kk = rem & 63;
    int k = chunk * 64 + kk;
    float v = 0.f;
    if (k < K_REAL) {
        int r = k / 28, c = k % 28;
        #pragma unroll
        for (int di = 0; di < 3; di++) {
            int oi = r - di;
            if (oi < 0 || oi > 25) continue;
            #pragma unroll
            for (int dj = 0; dj < 3; dj++) {
                int oj = c - dj;
                if (oj < 0 || oj > 25) continue;
                v += conv_w[di * 3 + dj] * w1[(oi * 26 + oj) * 128 + n];
            }
        }
    }
    uint32_t sw = sw128((uint32_t)(n * 128 + kk * 2));
    g_B[chunk][sw >> 1] = __float2half_rn(v);
}

// ============================================================================
// Main kernel. 8 warps: mg = wid&1 (m32), ng = wid>>1 (n32).
// ============================================================================
__global__ __launch_bounds__(THREADS, 2)
void digitconv_main(const float* __restrict__ x, const float* __restrict__ b1,
                    const float* __restrict__ w2, const float* __restrict__ b2,
                    float* __restrict__ out) {
    extern __shared__ char smem[];
    const uint32_t sbase = smem_u32(smem);
    const int tid = threadIdx.x;
    const int wid = tid >> 5;
    const int lane = tid & 31;
    const int wm = (wid & 1) * 32;       // 2 m-groups of 32
    const int wn = (wid >> 1) * 32;      // 4 n-groups of 32
    const size_t m0 = (size_t)blockIdx.x * BM;

    float* b1s  = (float*)(smem + SM_B1);
    float* w2s  = (float*)(smem + SM_W2);
    float* pacc = (float*)(smem + SM_PACC);

    if (tid < 128) b1s[tid] = b1[tid];
    for (int i = tid; i < 1280; i += THREADS) w2s[i] = w2[i];
    for (int i = tid; i < BM * 10; i += THREADS) pacc[i] = 0.f;

    float acc[2][4][4];
    #pragma unroll
    for (int tm = 0; tm < 2; tm++)
        #pragma unroll
        for (int tn = 0; tn < 4; tn++)
            #pragma unroll
            for (int e = 0; e < 4; e++) acc[tm][tn][e] = 0.f;

    // per-thread A addressing: i = q*256+tid, sub=i>>10, row=(i&1023)>>4, c4=i&15
    const int i_lo = tid;
    float4 areg[8];

    auto ldg_pair = [&](int p) {
        #pragma unroll
        for (int q = 0; q < 8; q++) {
            int i = q * THREADS + i_lo;
            int sub = i >> 10;
            int rem = i & 1023;
            int row = rem >> 4;
            int c4 = rem & 15;
            int gcol = p * 128 + sub * 64 + c4 * 4;
            if (gcol < K_REAL)
                areg[q] = *reinterpret_cast<const float4*>(x + (m0 + row) * K_REAL + gcol);
            else
                areg[q] = make_float4(0.f, 0.f, 0.f, 0.f);
        }
    };
    auto sts_pair = [&](uint32_t st) {
        #pragma unroll
        for (int q = 0; q < 8; q++) {
            int i = q * THREADS + i_lo;
            int sub = i >> 10;
            int rem = i & 1023;
            int row = rem >> 4;
            int c4 = rem & 15;
            __half2 h0 = __floats2half2_rn(areg[q].x, areg[q].y);
            __half2 h1 = __floats2half2_rn(areg[q].z, areg[q].w);
            uint2 w;
            w.x = *reinterpret_cast<uint32_t*>(&h0);
            w.y = *reinterpret_cast<uint32_t*>(&h1);
            uint32_t dst = st + A16_OFF + sub * 8192 + sw128((uint32_t)(row * 128 + c4 * 8));
            asm volatile("st.shared.v2.b32 [%0], {%1, %2};" :: "r"(dst), "r"(w.x), "r"(w.y)
                         : "memory");
        }
    };
    auto issue_b = [&](int p, uint32_t st) {
        const char* gb = (const char*)&g_B[2 * p][0];   // 32KB contiguous (2 chunks)
        #pragma unroll
        for (int q = 0; q < 8; q++) {
            int i = q * THREADS + i_lo;
            cp_async16(st + B_OFF + i * 16, gb + i * 16);
        }
        cp_commit();
    };

    // prologue: A(0) regs, B(0) -> stage 0
    ldg_pair(0);
    issue_b(0, sbase);

    const int sel = lane >> 3;

    for (int c = 0; c < NPAIR; c++) {
        const int s = c & 1;
        const uint32_t st  = sbase + s * STAGE_BYTES;
        const uint32_t st2 = sbase + (s ^ 1) * STAGE_BYTES;

        // Top barrier: all warps finished MMA(c-1) (stage s') and MMA(c-2) (stage s).
        __syncthreads();
        if (c + 1 < NPAIR) issue_b(c + 1, st2);   // prefetch next B into the free stage
        sts_pair(st);                              // A16(c) into current stage
        if (c + 1 < NPAIR) ldg_pair(c + 1);        // A(c+1) into registers (overlaps MMA)

        // pending groups: {B(c), B(c+1)} -> need B(c) complete
        if (c + 1 < NPAIR)
            asm volatile("cp.async.wait_group 1;" ::: "memory");
        else
            asm volatile("cp.async.wait_group 0;" ::: "memory");
        __syncthreads();                           // A16/B of stage s ready for all

        #pragma unroll
        for (int sub = 0; sub < 2; sub++) {
            const uint32_t aB = st + A16_OFF + sub * 8192;
            const uint32_t bB = st + B_OFF + sub * 16384;
            #pragma unroll
            for (int ks = 0; ks < 4; ks++) {
                uint32_t afr[2][4];
                #pragma unroll
                for (int tm = 0; tm < 2; tm++) {
                    int r = wm + tm * 16 + (lane & 7) + ((sel & 1) << 3);
                    int kb = ks * 32 + ((sel >> 1) << 4);
                    ldmatrix_x4(afr[tm][0], afr[tm][1], afr[tm][2], afr[tm][3],
                                aB + sw128((uint32_t)(r * 128 + kb)));
                }
                uint32_t bf[4][2];
                #pragma unroll
                for (int tp = 0; tp < 2; tp++) {
                    int r = wn + (2 * tp + (sel >> 1)) * 8 + (lane & 7);
                    int kb = ks * 32 + ((sel & 1) << 4);
                    ldmatrix_x4(bf[2*tp][0], bf[2*tp][1], bf[2*tp+1][0], bf[2*tp+1][1],
                                bB + sw128((uint32_t)(r * 128 + kb)));
                }
                #pragma unroll
                for (int tm = 0; tm < 2; tm++)
                    #pragma unroll
                    for (int tn = 0; tn < 4; tn++)
                        mma16816(acc[tm][tn], afr[tm], bf[tn]);
            }
        }
    }

    // ---- Epilogue: relu(D + b1) @ w2, reduce, + b2, store ----
    #pragma unroll
    for (int tm = 0; tm < 2; tm++) {
        #pragma unroll
        for (int half = 0; half < 2; half++) {
            float p[10];
            #pragma unroll
            for (int j = 0; j < 10; j++) p[j] = 0.f;
            int r = wm + tm * 16 + (lane >> 2) + half * 8;
            #pragma unroll
            for (int tn = 0; tn < 4; tn++) {
                #pragma unroll
                for (int e = 0; e < 2; e++) {
                    int col = wn + tn * 8 + ((lane & 3) << 1) + e;
                    float v = acc[tm][tn][half * 2 + e] + b1s[col];
                    v = fmaxf(v, 0.f);
                    #pragma unroll
                    for (int j = 0; j < 10; j++) p[j] = fmaf(v, w2s[col * 10 + j], p[j]);
                }
            }
            #pragma unroll
            for (int j = 0; j < 10; j++) {
                p[j] += __shfl_xor_sync(0xFFFFFFFF, p[j], 1);
                p[j] += __shfl_xor_sync(0xFFFFFFFF, p[j], 2);
            }
            if ((lane & 3) == 0) {
                #pragma unroll
                for (int j = 0; j < 10; j++) atomicAdd(&pacc[r * 10 + j], p[j]);
            }
        }
    }
    __syncthreads();

    for (int i = tid; i < BM * 10; i += THREADS) {
        int r = i / 10, j = i - r * 10;
        out[(m0 + r) * 10 + j] = pacc[i] + __ldg(&b2[j]);
    }
}

// ============================================================================
extern "C" void kernel_launch(void* const* d_in, const int* in_sizes, int n_in,
                              void* d_out, int out_size) {
    const float* x      = (const float*)d_in[0];
    const float* conv_w = (const float*)d_in[1];
    const float* w1     = (const float*)d_in[2];
    const float* b1     = (const float*)d_in[3];
    const float* w2     = (const float*)d_in[4];
    const float* b2     = (const float*)d_in[5];
    float* out = (float*)d_out;

    cudaFuncSetAttribute(digitconv_main,
                         cudaFuncAttributeMaxDynamicSharedMemorySize, SMEM_TOTAL);

    prep_kernel<<<(NCH64 * 128 * 64 + 255) / 256, 256>>>(conv_w, w1);
    digitconv_main<<<B_ROWS / BM, THREADS, SMEM_TOTAL>>>(x, b1, w2, b2, out);
}